// round 13
// baseline (speedup 1.0000x reference)
#include <cuda_runtime.h>
#include <cuda_bf16.h>
#include <cstdint>

// Problem constants
#define Bc   8
#define Nn   2048
#define Kn   32
#define Fin  256
#define Cch  512
#define Mrows 16384
#define Kimg 512            // physical image: [hi(256) | lo(256)]
#define KIT  12             // logical K chunks of 64 (A: hi,lo,hi ; W: hi,hi,lo)

// ---------------------------------------------------------------------------
// Device-global scratch (no allocations allowed)
// ---------------------------------------------------------------------------
__device__ __align__(16) __nv_bfloat16 g_Aself[Mrows * Kimg];   // 16.8 MB
__device__ __align__(16) __nv_bfloat16 g_Wbf[2][256 * Kimg];    // contiguous [512, Kimg]
__device__ __align__(16) float g_Hn[Mrows * 256];               // 16.8 MB (x·Wn^T)
__device__ float g_stats[2 * Cch];   // zero-initialized; epilogue self-cleans
__device__ int   g_bar0;             // grid barrier counter (self-cleaned)
__device__ int   g_done;             // finalize-read counter (self-cleaned)

// ---------------------------------------------------------------------------
// bf16 hi/lo split of a float4 -> two 8B packets
// ---------------------------------------------------------------------------
__device__ __forceinline__ void split4(float4 m, uint2& hv, uint2& lv) {
    float f[4] = {m.x, m.y, m.z, m.w};
    unsigned short h[4], l[4];
#pragma unroll
    for (int j = 0; j < 4; j++) {
        __nv_bfloat16 hb = __float2bfloat16_rn(f[j]);
        h[j] = __bfloat16_as_ushort(hb);
        l[j] = __bfloat16_as_ushort(__float2bfloat16_rn(f[j] - __bfloat162float(hb)));
    }
    hv = make_uint2((uint32_t)h[0] | ((uint32_t)h[1] << 16),
                    (uint32_t)h[2] | ((uint32_t)h[3] << 16));
    lv = make_uint2((uint32_t)l[0] | ((uint32_t)l[1] << 16),
                    (uint32_t)l[2] | ((uint32_t)l[3] << 16));
}

// ---------------------------------------------------------------------------
// Convert x (fp32 [Mrows][256]) -> bf16 split image [hi | lo], row-major.
// ---------------------------------------------------------------------------
__global__ __launch_bounds__(256) void convA_kernel(const float* __restrict__ src)
{
    int gid = blockIdx.x * 256 + threadIdx.x;      // Mrows*32
    int m = gid >> 5, kg = gid & 31, k0 = kg * 8;
    const float4* s4 = (const float4*)src + (size_t)m * 64 + kg * 2;
    float4 f0 = s4[0], f1 = s4[1];
    uint2 hv0, lv0, hv1, lv1;
    split4(f0, hv0, lv0);
    split4(f1, hv1, lv1);
    __nv_bfloat16* o = g_Aself + (size_t)m * Kimg;
    *(uint4*)(o + k0)       = make_uint4(hv0.x, hv0.y, hv1.x, hv1.y);
    *(uint4*)(o + 256 + k0) = make_uint4(lv0.x, lv0.y, lv1.x, lv1.y);
}

// ---------------------------------------------------------------------------
// Convert BOTH W (fp32 [256][256]) -> bf16 split images [hi | lo].
// Result is a contiguous [512, Kimg] image: rows 0-255 = Wx, 256-511 = Wn.
// ---------------------------------------------------------------------------
__global__ __launch_bounds__(256) void convW_kernel(
    const float* __restrict__ wx, const float* __restrict__ wn)
{
    int g = blockIdx.x >> 5;
    const float* w = g ? wn : wx;
    int gid = (blockIdx.x & 31) * 256 + threadIdx.x;   // 8192
    int o_ = gid >> 5, kg = gid & 31, k0 = kg * 8;
    const float4* s4 = (const float4*)w + (size_t)o_ * 64 + kg * 2;
    float4 f0 = s4[0], f1 = s4[1];
    uint2 hv0, lv0, hv1, lv1;
    split4(f0, hv0, lv0);
    split4(f1, hv1, lv1);
    __nv_bfloat16* dst = g_Wbf[g] + (size_t)o_ * Kimg;
    *(uint4*)(dst + k0)       = make_uint4(hv0.x, hv0.y, hv1.x, hv1.y);
    *(uint4*)(dst + 256 + k0) = make_uint4(lv0.x, lv0.y, lv1.x, lv1.y);
}

// ---------------------------------------------------------------------------
// bf16 GEMM via mma.sync (HMMA), 3-term split via chunk remap:
//   logical it 0-3:  A_hi x W_hi    it 4-7: A_lo x W_hi    it 8-11: A_hi x W_lo
// BM=128, BN=128, BK=64, 256 threads (2m x 4n warps), warp tile 64x32.
// n-block nb = blockIdx.y + nbase (0..3 over the [512,Kimg] W image):
//   nb 0,1 -> out cols 0-255 (bias_x, stride 512)
//   nb 2,3 -> g_Hn cols 0-255 (bias_n, stride 256)
// ---------------------------------------------------------------------------
#define BM 128
#define BN 128
#define BK 64
#define SLD 72
#define A_ST_ELT (BM * SLD)             // 9216
#define B_ST_ELT (BN * SLD)             // 9216
#define A_ST_B   (A_ST_ELT * 2)
#define B_ST_B   (B_ST_ELT * 2)
#define NSTG 3
#define GEMM_SMEM ((A_ST_ELT + B_ST_ELT) * NSTG * 2)   // 110592 bytes

__device__ __forceinline__ uint32_t smem_u32(const void* p) {
    uint32_t a;
    asm("{ .reg .u64 t; cvta.to.shared.u64 t, %1; cvt.u32.u64 %0, t; }" : "=r"(a) : "l"(p));
    return a;
}
#define CP16(dst, src) \
    asm volatile("cp.async.cg.shared.global [%0], [%1], 16;" :: "r"(dst), "l"(src))
#define CP_COMMIT() asm volatile("cp.async.commit_group;")
#define CP_WAIT2()  asm volatile("cp.async.wait_group 2;")

__global__ __launch_bounds__(256, 2) void gemm_mma_kernel(
    const __nv_bfloat16* __restrict__ Abf, const __nv_bfloat16* __restrict__ Wbf,
    const float* __restrict__ bias_x, const float* __restrict__ bias_n,
    float* __restrict__ out, float* __restrict__ Hn, int nbase)
{
    extern __shared__ __align__(16) __nv_bfloat16 sm[];
    __nv_bfloat16* As0 = sm;
    __nv_bfloat16* Bs0 = sm + NSTG * A_ST_ELT;

    const int tid = threadIdx.x;
    const int lane = tid & 31, wid = tid >> 5;
    const int wm = wid >> 2, wn = wid & 3;          // 2 x 4 warp grid
    const int m0 = blockIdx.x * BM;
    const int nb = blockIdx.y + nbase;              // 0..3
    const int n0 = nb * BN;                         // row into [512,Kimg] W image

    // destination select
    const float* bias = (nb < 2) ? (bias_x + n0) : (bias_n + (n0 - 256));
    float* Cp         = (nb < 2) ? (out + n0)    : (Hn + (n0 - 256));
    const int cstride = (nb < 2) ? Cch : 256;

    // --- cp.async: A and B each 1024 16B-chunks -> 4/thread, stride 32 rows ---
    const int lrow = tid >> 3, lcol = (tid & 7) * 8;
    const __nv_bfloat16* aSrc = Abf + (size_t)(m0 + lrow) * Kimg + lcol;
    const __nv_bfloat16* bSrc = Wbf + (size_t)(n0 + lrow) * Kimg + lcol;
    const uint32_t dA0 = smem_u32(&As0[lrow * SLD + lcol]);
    const uint32_t dB0 = smem_u32(&Bs0[lrow * SLD + lcol]);
    const int srcStep = 32 * Kimg;                  // elements per i-step
    const int dstStep = 32 * SLD * 2;               // bytes per i-step

    // --- ldmatrix per-thread base addresses (stage 0) ---
    const int l16 = lane & 15, lhi = (lane >> 4) * 8;
    const uint32_t aAddr0 = smem_u32(&As0[(wm * 64 + l16) * SLD + lhi]);
    const uint32_t bAddr0 = smem_u32(&Bs0[(wn * 32 + l16) * SLD + lhi]);

    float d[4][4][4];
#pragma unroll
    for (int mi = 0; mi < 4; mi++)
#pragma unroll
        for (int ni = 0; ni < 4; ni++)
#pragma unroll
            for (int q = 0; q < 4; q++) d[mi][ni][q] = 0.0f;

    // preload stages 0,1,2 (it 0..2: A chunk = it, W chunk = it)
#pragma unroll
    for (int st = 0; st < NSTG; st++) {
        int k0 = st * BK;
#pragma unroll
        for (int i = 0; i < 4; i++) {
            CP16(dA0 + st * A_ST_B + i * dstStep, aSrc + i * srcStep + k0);
            CP16(dB0 + st * B_ST_B + i * dstStep, bSrc + i * srcStep + k0);
        }
        CP_COMMIT();
    }

    int st = 0;
#pragma unroll 1
    for (int it = 0; it < KIT; it++) {
        CP_WAIT2();
        __syncthreads();

        const uint32_t aA = aAddr0 + st * A_ST_B;
        const uint32_t bA = bAddr0 + st * B_ST_B;
#pragma unroll
        for (int s = 0; s < 4; s++) {               // four k16 steps
            uint32_t a[4][4], b[4][2];
#pragma unroll
            for (int mi = 0; mi < 4; mi++) {
                uint32_t addr = aA + mi * (16 * SLD * 2) + s * 32;
                asm volatile("ldmatrix.sync.aligned.m8n8.x4.shared.b16 {%0,%1,%2,%3}, [%4];"
                             : "=r"(a[mi][0]), "=r"(a[mi][1]), "=r"(a[mi][2]), "=r"(a[mi][3])
                             : "r"(addr));
            }
#pragma unroll
            for (int ng = 0; ng < 2; ng++) {        // 16 n-cols per x4
                uint32_t r0, r1, r2, r3;
                uint32_t addr = bA + ng * (16 * SLD * 2) + s * 32;
                asm volatile("ldmatrix.sync.aligned.m8n8.x4.shared.b16 {%0,%1,%2,%3}, [%4];"
                             : "=r"(r0), "=r"(r1), "=r"(r2), "=r"(r3) : "r"(addr));
                b[2 * ng + 0][0] = r0; b[2 * ng + 0][1] = r2;
                b[2 * ng + 1][0] = r1; b[2 * ng + 1][1] = r3;
            }
#pragma unroll
            for (int mi = 0; mi < 4; mi++)
#pragma unroll
                for (int ni = 0; ni < 4; ni++)
                    asm volatile(
                        "mma.sync.aligned.m16n8k16.row.col.f32.bf16.bf16.f32 "
                        "{%0,%1,%2,%3}, {%4,%5,%6,%7}, {%8,%9}, {%0,%1,%2,%3};"
                        : "+f"(d[mi][ni][0]), "+f"(d[mi][ni][1]),
                          "+f"(d[mi][ni][2]), "+f"(d[mi][ni][3])
                        : "r"(a[mi][0]), "r"(a[mi][1]), "r"(a[mi][2]), "r"(a[mi][3]),
                          "r"(b[ni][0]), "r"(b[ni][1]));
        }
        __syncthreads();
        if (it + NSTG < KIT) {
            int j = it + NSTG;
            int kA = (j < 8 ? j : j - 8) * BK;
            int kB = (j < 8 ? (j & 3) : j - 4) * BK;
#pragma unroll
            for (int i = 0; i < 4; i++) {
                CP16(dA0 + st * A_ST_B + i * dstStep, aSrc + i * srcStep + kA);
                CP16(dB0 + st * B_ST_B + i * dstStep, bSrc + i * srcStep + kB);
            }
        }
        CP_COMMIT();
        st = (st == NSTG - 1) ? 0 : st + 1;
    }

    // epilogue: D frag -> dest with bias (local cols 0..127)
    const int quad = lane >> 2, tq = lane & 3;
#pragma unroll
    for (int mi = 0; mi < 4; mi++) {
        int row = m0 + wm * 64 + mi * 16 + quad;
#pragma unroll
        for (int ni = 0; ni < 4; ni++) {
            int col = wn * 32 + ni * 8 + tq * 2;
            float2 bv = *(const float2*)(bias + col);
            float2 v0 = make_float2(d[mi][ni][0] + bv.x, d[mi][ni][1] + bv.y);
            float2 v1 = make_float2(d[mi][ni][2] + bv.x, d[mi][ni][3] + bv.y);
            *(float2*)&Cp[(size_t)row * cstride + col] = v0;
            *(float2*)&Cp[(size_t)(row + 8) * cstride + col] = v1;
        }
    }
}

// ---------------------------------------------------------------------------
// Gather-mean over Hn rows (post-GEMM): out[(b,n), 256:512] = mean_k Hn[b,idx[n,k],:]
// One block per n; 512 threads = 64 float4-lanes x 8 batches.
// ---------------------------------------------------------------------------
__global__ __launch_bounds__(512, 2) void gather_out_kernel(
    const float* __restrict__ Hn, const int* __restrict__ idx,
    float* __restrict__ out)
{
    __shared__ int sidx[Kn];
    const int n = blockIdx.x, t = threadIdx.x;
    if (t < Kn) sidx[t] = idx[n * Kn + t] * 64;   // prescaled float4 row offset
    __syncthreads();

    const int f4 = t & 63;
    const int b  = t >> 6;             // 0..7
    const float4* hb = (const float4*)Hn + (size_t)b * Nn * 64 + f4;

    float4 a0 = {0,0,0,0}, a1 = {0,0,0,0}, a2 = {0,0,0,0}, a3 = {0,0,0,0};
#pragma unroll
    for (int k = 0; k < Kn; k += 4) {
        float4 v0 = hb[sidx[k + 0]];
        float4 v1 = hb[sidx[k + 1]];
        float4 v2 = hb[sidx[k + 2]];
        float4 v3 = hb[sidx[k + 3]];
        a0.x += v0.x; a0.y += v0.y; a0.z += v0.z; a0.w += v0.w;
        a1.x += v1.x; a1.y += v1.y; a1.z += v1.z; a1.w += v1.w;
        a2.x += v2.x; a2.y += v2.y; a2.z += v2.z; a2.w += v2.w;
        a3.x += v3.x; a3.y += v3.y; a3.z += v3.z; a3.w += v3.w;
    }
    const float s = 1.0f / Kn;
    float4 m = make_float4(((a0.x + a1.x) + (a2.x + a3.x)) * s,
                           ((a0.y + a1.y) + (a2.y + a3.y)) * s,
                           ((a0.z + a1.z) + (a2.z + a3.z)) * s,
                           ((a0.w + a1.w) + (a2.w + a3.w)) * s);
    ((float4*)(out + ((size_t)b * Nn + n) * Cch + 256))[f4] = m;
}

// ---------------------------------------------------------------------------
// Persistent fused epilogue (unchanged).
// ---------------------------------------------------------------------------
#define EPI_BLOCKS 128
#define EPI_ROWS   (Mrows / EPI_BLOCKS)   // 128 rows per block, 16 per warp

__global__ __launch_bounds__(256) void epilogue_kernel(
    const float* __restrict__ gamma, const float* __restrict__ beta,
    float* __restrict__ h)
{
    __shared__ float ssum[Cch], ssq[Cch];
    __shared__ float sinv[EPI_ROWS];
    __shared__ float sc[Cch], sh[Cch];
    __shared__ int slast;
    const int tid = threadIdx.x, lane = tid & 31, wid = tid >> 5;
    ssum[tid] = 0.f; ssq[tid] = 0.f;
    ssum[tid + 256] = 0.f; ssq[tid + 256] = 0.f;
    __syncthreads();

    float asum[4][4], asq[4][4];
#pragma unroll
    for (int q = 0; q < 4; q++)
#pragma unroll
        for (int j = 0; j < 4; j++) { asum[q][j] = 0.f; asq[q][j] = 0.f; }

    const int rbase = wid * 16;
    const int row0 = blockIdx.x * EPI_ROWS + rbase;
#pragma unroll 1
    for (int r = 0; r < 16; r++) {
        const float4* p = (const float4*)(h + (size_t)(row0 + r) * Cch);
        float4 v[4];
#pragma unroll
        for (int q = 0; q < 4; q++) v[q] = p[lane + 32 * q];
        float s = 0.f;
#pragma unroll
        for (int q = 0; q < 4; q++)
            s += v[q].x * v[q].x + v[q].y * v[q].y + v[q].z * v[q].z + v[q].w * v[q].w;
#pragma unroll
        for (int o = 16; o; o >>= 1) s += __shfl_xor_sync(0xffffffffu, s, o);
        float inv = 1.0f / fmaxf(sqrtf(s), 1e-12f);
        if (lane == 0) sinv[rbase + r] = inv;
#pragma unroll
        for (int q = 0; q < 4; q++) {
            float u[4] = {v[q].x, v[q].y, v[q].z, v[q].w};
#pragma unroll
            for (int j = 0; j < 4; j++) {
                float t = fmaxf(u[j] * inv, 0.0f);
                asum[q][j] += t;
                asq[q][j]  += t * t;
            }
        }
    }
#pragma unroll
    for (int q = 0; q < 4; q++)
#pragma unroll
        for (int j = 0; j < 4; j++) {
            int c = 4 * lane + 128 * q + j;
            atomicAdd(&ssum[c], asum[q][j]);
            atomicAdd(&ssq[c],  asq[q][j]);
        }
    __syncthreads();
    for (int c = tid; c < Cch; c += 256) {
        atomicAdd(&g_stats[c],       ssum[c]);
        atomicAdd(&g_stats[Cch + c], ssq[c]);
    }

    // ---- grid barrier ----
    __threadfence();
    __syncthreads();
    if (tid == 0) {
        atomicAdd(&g_bar0, 1);
        while (*(volatile int*)&g_bar0 < EPI_BLOCKS) { }
    }
    __syncthreads();
    __threadfence();

    // ---- finalize (every block; values into smem) ----
    const float invM = 1.0f / (float)Mrows;
    for (int c = tid; c < Cch; c += 256) {
        float mu  = g_stats[c] * invM;
        float var = g_stats[Cch + c] * invM - mu * mu;
        float s   = gamma[c] * rsqrtf(var + 1e-5f);
        sc[c] = s;
        sh[c] = beta[c] - mu * s;
    }
    __syncthreads();

    // ---- self-clean: last block to finish reading zeroes stats + counters ----
    if (tid == 0) slast = (atomicAdd(&g_done, 1) == EPI_BLOCKS - 1);
    __syncthreads();
    if (slast) {
        for (int c = tid; c < 2 * Cch; c += 256) g_stats[c] = 0.f;
        if (tid == 0) { g_bar0 = 0; g_done = 0; }
    }

    // ---- phase 2: apply on the same rows ----
#pragma unroll 1
    for (int r = 0; r < 16; r++) {
        const float inv = sinv[rbase + r];
        float4* p = (float4*)(h + (size_t)(row0 + r) * Cch);
#pragma unroll
        for (int q = 0; q < 4; q++) {
            float4 v = p[lane + 32 * q];
            int c = 4 * lane + 128 * q;
            v.x = fmaxf(v.x * inv, 0.f) * sc[c + 0] + sh[c + 0];
            v.y = fmaxf(v.y * inv, 0.f) * sc[c + 1] + sh[c + 1];
            v.z = fmaxf(v.z * inv, 0.f) * sc[c + 2] + sh[c + 2];
            v.w = fmaxf(v.w * inv, 0.f) * sc[c + 3] + sh[c + 3];
            p[lane + 32 * q] = v;
        }
    }
}

// ---------------------------------------------------------------------------
// Launch
// Inputs: x, idx_neib, Wx_w, Wx_b, Wn_w, Wn_b, gamma, beta
// ---------------------------------------------------------------------------
extern "C" void kernel_launch(void* const* d_in, const int* in_sizes, int n_in,
                              void* d_out, int out_size)
{
    const float* x     = (const float*)d_in[0];
    const int*   idx   = (const int*)  d_in[1];
    const float* Wx_w  = (const float*)d_in[2];
    const float* Wx_b  = (const float*)d_in[3];
    const float* Wn_w  = (const float*)d_in[4];
    const float* Wn_b  = (const float*)d_in[5];
    const float* gamma = (const float*)d_in[6];
    const float* beta  = (const float*)d_in[7];
    float* out = (float*)d_out;

    static cudaStream_t s2 = nullptr;
    static cudaEvent_t ev_n = nullptr, ev_join = nullptr;
    static int stream_ok = -1;
    if (stream_ok < 0) {
        bool ok = cudaFuncSetAttribute(gemm_mma_kernel,
                     cudaFuncAttributeMaxDynamicSharedMemorySize, GEMM_SMEM) == cudaSuccess;
        ok = ok && cudaStreamCreateWithFlags(&s2, cudaStreamNonBlocking) == cudaSuccess;
        ok = ok && cudaEventCreateWithFlags(&ev_n, cudaEventDisableTiming) == cudaSuccess;
        ok = ok && cudaEventCreateWithFlags(&ev_join, cudaEventDisableTiming) == cudaSuccess;
        stream_ok = ok ? 1 : 0;
    }

    __nv_bfloat16* Wimg;  cudaGetSymbolAddress((void**)&Wimg, g_Wbf);   // [512, Kimg]
    __nv_bfloat16* Aself; cudaGetSymbolAddress((void**)&Aself, g_Aself);
    float* Hn; cudaGetSymbolAddress((void**)&Hn, g_Hn);

    dim3 hgrid(Mrows / BM, 2);   // one 256-column half

    // operand prep (serial on main; ~8us)
    convW_kernel<<<64, 256>>>(Wx_w, Wn_w);
    convA_kernel<<<2048, 256>>>(x);

    // neighbor half first: Hn = x * Wn^T + bn
    gemm_mma_kernel<<<hgrid, 256, GEMM_SMEM>>>(Aself, Wimg, Wx_b, Wn_b, out, Hn, 2);

    if (stream_ok) {
        // overlap: gather (L2-bound, reads Hn) with self-half GEMM (tensor-bound)
        cudaEventRecord(ev_n, 0);
        cudaStreamWaitEvent(s2, ev_n, 0);
        gather_out_kernel<<<Nn, 512, 0, s2>>>(Hn, idx, out);
        gemm_mma_kernel<<<hgrid, 256, GEMM_SMEM>>>(Aself, Wimg, Wx_b, Wn_b, out, Hn, 0);
        cudaEventRecord(ev_join, s2);
        cudaStreamWaitEvent(0, ev_join, 0);
    } else {
        gather_out_kernel<<<Nn, 512>>>(Hn, idx, out);
        gemm_mma_kernel<<<hgrid, 256, GEMM_SMEM>>>(Aself, Wimg, Wx_b, Wn_b, out, Hn, 0);
    }

    epilogue_kernel<<<EPI_BLOCKS, 256>>>(gamma, beta, out);
}

// round 14
// speedup vs baseline: 1.0568x; 1.0568x over previous
#include <cuda_runtime.h>
#include <cuda_bf16.h>
#include <cstdint>

// Problem constants
#define Bc   8
#define Nn   2048
#define Kn   32
#define Fin  256
#define Cch  512
#define Mrows 16384
#define Kimg 512            // physical image: [hi(256) | lo(256)]
#define KIT  12             // logical K chunks of 64 (A: hi,lo,hi ; W: hi,hi,lo)

// ---------------------------------------------------------------------------
// Device-global scratch (no allocations allowed)
// ---------------------------------------------------------------------------
__device__ __align__(16) __nv_bfloat16 g_Aself[Mrows * Kimg];   // 16.8 MB
__device__ __align__(16) __nv_bfloat16 g_Wbf[2][256 * Kimg];    // contiguous [512, Kimg]
__device__ __align__(16) float g_Hn[Mrows * 256];               // 16.8 MB (x·Wn^T)
__device__ float g_stats[2 * Cch];   // zero-initialized; epilogue self-cleans
__device__ int   g_bar0;             // grid barrier counter (self-cleaned)
__device__ int   g_done;             // finalize-read counter (self-cleaned)

// ---------------------------------------------------------------------------
// bf16 hi/lo split of a float4 -> two 8B packets
// ---------------------------------------------------------------------------
__device__ __forceinline__ void split4(float4 m, uint2& hv, uint2& lv) {
    float f[4] = {m.x, m.y, m.z, m.w};
    unsigned short h[4], l[4];
#pragma unroll
    for (int j = 0; j < 4; j++) {
        __nv_bfloat16 hb = __float2bfloat16_rn(f[j]);
        h[j] = __bfloat16_as_ushort(hb);
        l[j] = __bfloat16_as_ushort(__float2bfloat16_rn(f[j] - __bfloat162float(hb)));
    }
    hv = make_uint2((uint32_t)h[0] | ((uint32_t)h[1] << 16),
                    (uint32_t)h[2] | ((uint32_t)h[3] << 16));
    lv = make_uint2((uint32_t)l[0] | ((uint32_t)l[1] << 16),
                    (uint32_t)l[2] | ((uint32_t)l[3] << 16));
}

// ---------------------------------------------------------------------------
// Convert x (fp32 [Mrows][256]) -> bf16 split image [hi | lo], row-major.
// ---------------------------------------------------------------------------
__global__ __launch_bounds__(256) void convA_kernel(const float* __restrict__ src)
{
    int gid = blockIdx.x * 256 + threadIdx.x;      // Mrows*32
    int m = gid >> 5, kg = gid & 31, k0 = kg * 8;
    const float4* s4 = (const float4*)src + (size_t)m * 64 + kg * 2;
    float4 f0 = s4[0], f1 = s4[1];
    uint2 hv0, lv0, hv1, lv1;
    split4(f0, hv0, lv0);
    split4(f1, hv1, lv1);
    __nv_bfloat16* o = g_Aself + (size_t)m * Kimg;
    *(uint4*)(o + k0)       = make_uint4(hv0.x, hv0.y, hv1.x, hv1.y);
    *(uint4*)(o + 256 + k0) = make_uint4(lv0.x, lv0.y, lv1.x, lv1.y);
}

// ---------------------------------------------------------------------------
// Convert BOTH W (fp32 [256][256]) -> bf16 split images [hi | lo].
// Result is a contiguous [512, Kimg] image: rows 0-255 = Wx, 256-511 = Wn.
// ---------------------------------------------------------------------------
__global__ __launch_bounds__(256) void convW_kernel(
    const float* __restrict__ wx, const float* __restrict__ wn)
{
    int g = blockIdx.x >> 5;
    const float* w = g ? wn : wx;
    int gid = (blockIdx.x & 31) * 256 + threadIdx.x;   // 8192
    int o_ = gid >> 5, kg = gid & 31, k0 = kg * 8;
    const float4* s4 = (const float4*)w + (size_t)o_ * 64 + kg * 2;
    float4 f0 = s4[0], f1 = s4[1];
    uint2 hv0, lv0, hv1, lv1;
    split4(f0, hv0, lv0);
    split4(f1, hv1, lv1);
    __nv_bfloat16* dst = g_Wbf[g] + (size_t)o_ * Kimg;
    *(uint4*)(dst + k0)       = make_uint4(hv0.x, hv0.y, hv1.x, hv1.y);
    *(uint4*)(dst + 256 + k0) = make_uint4(lv0.x, lv0.y, lv1.x, lv1.y);
}

// ---------------------------------------------------------------------------
// bf16 GEMM via mma.sync (HMMA), 3-term split via chunk remap:
//   logical it 0-3:  A_hi x W_hi    it 4-7: A_lo x W_hi    it 8-11: A_hi x W_lo
// BM=128, BN=128, BK=64, 256 threads (2m x 4n warps), warp tile 64x32.
// PERSISTENT over nreps n-tiles: nb = nbase + blockIdx.y*nreps + r.
//   nb 0,1 -> out cols 0-255 (bias_x, stride 512)
//   nb 2,3 -> g_Hn cols 0-255 (bias_n, stride 256)
// Self-GEMM: grid (128,1), nreps=2 -> exactly 1 CTA/SM, leaves room for the
// gather kernel to co-reside (regs: 256x~110 = 28K of 64K per SM).
// ---------------------------------------------------------------------------
#define BM 128
#define BN 128
#define BK 64
#define SLD 72
#define A_ST_ELT (BM * SLD)             // 9216
#define B_ST_ELT (BN * SLD)             // 9216
#define A_ST_B   (A_ST_ELT * 2)
#define B_ST_B   (B_ST_ELT * 2)
#define NSTG 3
#define GEMM_SMEM ((A_ST_ELT + B_ST_ELT) * NSTG * 2)   // 110592 bytes

__device__ __forceinline__ uint32_t smem_u32(const void* p) {
    uint32_t a;
    asm("{ .reg .u64 t; cvta.to.shared.u64 t, %1; cvt.u32.u64 %0, t; }" : "=r"(a) : "l"(p));
    return a;
}
#define CP16(dst, src) \
    asm volatile("cp.async.cg.shared.global [%0], [%1], 16;" :: "r"(dst), "l"(src))
#define CP_COMMIT() asm volatile("cp.async.commit_group;")
#define CP_WAIT2()  asm volatile("cp.async.wait_group 2;")

__global__ __launch_bounds__(256, 2) void gemm_mma_kernel(
    const __nv_bfloat16* __restrict__ Abf, const __nv_bfloat16* __restrict__ Wbf,
    const float* __restrict__ bias_x, const float* __restrict__ bias_n,
    float* __restrict__ out, float* __restrict__ Hn, int nbase, int nreps)
{
    extern __shared__ __align__(16) __nv_bfloat16 sm[];
    __nv_bfloat16* As0 = sm;
    __nv_bfloat16* Bs0 = sm + NSTG * A_ST_ELT;

    const int tid = threadIdx.x;
    const int lane = tid & 31, wid = tid >> 5;
    const int wm = wid >> 2, wn = wid & 3;          // 2 x 4 warp grid
    const int m0 = blockIdx.x * BM;

    // --- A-side cp.async (fixed across reps) ---
    const int lrow = tid >> 3, lcol = (tid & 7) * 8;
    const __nv_bfloat16* aSrc = Abf + (size_t)(m0 + lrow) * Kimg + lcol;
    const uint32_t dA0 = smem_u32(&As0[lrow * SLD + lcol]);
    const uint32_t dB0 = smem_u32(&Bs0[lrow * SLD + lcol]);
    const int srcStep = 32 * Kimg;                  // elements per i-step
    const int dstStep = 32 * SLD * 2;               // bytes per i-step

    // --- ldmatrix per-thread base addresses (stage 0) ---
    const int l16 = lane & 15, lhi = (lane >> 4) * 8;
    const uint32_t aAddr0 = smem_u32(&As0[(wm * 64 + l16) * SLD + lhi]);
    const uint32_t bAddr0 = smem_u32(&Bs0[(wn * 32 + l16) * SLD + lhi]);

#pragma unroll 1
    for (int rep = 0; rep < nreps; rep++) {
        const int nb = nbase + blockIdx.y * nreps + rep;   // 0..3
        const int n0 = nb * BN;                            // row into [512,Kimg] W image
        const float* bias = (nb < 2) ? (bias_x + n0) : (bias_n + (n0 - 256));
        float* Cp         = (nb < 2) ? (out + n0)    : (Hn + (n0 - 256));
        const int cstride = (nb < 2) ? Cch : 256;
        const __nv_bfloat16* bSrc = Wbf + (size_t)(n0 + lrow) * Kimg + lcol;

        float d[4][4][4];
#pragma unroll
        for (int mi = 0; mi < 4; mi++)
#pragma unroll
            for (int ni = 0; ni < 4; ni++)
#pragma unroll
                for (int q = 0; q < 4; q++) d[mi][ni][q] = 0.0f;

        __syncthreads();   // smem safe to overwrite (prior rep fully consumed)

        // preload stages 0,1,2 (it 0..2: A chunk = it, W chunk = it)
#pragma unroll
        for (int st = 0; st < NSTG; st++) {
            int k0 = st * BK;
#pragma unroll
            for (int i = 0; i < 4; i++) {
                CP16(dA0 + st * A_ST_B + i * dstStep, aSrc + i * srcStep + k0);
                CP16(dB0 + st * B_ST_B + i * dstStep, bSrc + i * srcStep + k0);
            }
            CP_COMMIT();
        }

        int st = 0;
#pragma unroll 1
        for (int it = 0; it < KIT; it++) {
            CP_WAIT2();
            __syncthreads();

            const uint32_t aA = aAddr0 + st * A_ST_B;
            const uint32_t bA = bAddr0 + st * B_ST_B;
#pragma unroll
            for (int s = 0; s < 4; s++) {               // four k16 steps
                uint32_t a[4][4], b[4][2];
#pragma unroll
                for (int mi = 0; mi < 4; mi++) {
                    uint32_t addr = aA + mi * (16 * SLD * 2) + s * 32;
                    asm volatile("ldmatrix.sync.aligned.m8n8.x4.shared.b16 {%0,%1,%2,%3}, [%4];"
                                 : "=r"(a[mi][0]), "=r"(a[mi][1]), "=r"(a[mi][2]), "=r"(a[mi][3])
                                 : "r"(addr));
                }
#pragma unroll
                for (int ng = 0; ng < 2; ng++) {        // 16 n-cols per x4
                    uint32_t r0, r1, r2, r3;
                    uint32_t addr = bA + ng * (16 * SLD * 2) + s * 32;
                    asm volatile("ldmatrix.sync.aligned.m8n8.x4.shared.b16 {%0,%1,%2,%3}, [%4];"
                                 : "=r"(r0), "=r"(r1), "=r"(r2), "=r"(r3) : "r"(addr));
                    b[2 * ng + 0][0] = r0; b[2 * ng + 0][1] = r2;
                    b[2 * ng + 1][0] = r1; b[2 * ng + 1][1] = r3;
                }
#pragma unroll
                for (int mi = 0; mi < 4; mi++)
#pragma unroll
                    for (int ni = 0; ni < 4; ni++)
                        asm volatile(
                            "mma.sync.aligned.m16n8k16.row.col.f32.bf16.bf16.f32 "
                            "{%0,%1,%2,%3}, {%4,%5,%6,%7}, {%8,%9}, {%0,%1,%2,%3};"
                            : "+f"(d[mi][ni][0]), "+f"(d[mi][ni][1]),
                              "+f"(d[mi][ni][2]), "+f"(d[mi][ni][3])
                            : "r"(a[mi][0]), "r"(a[mi][1]), "r"(a[mi][2]), "r"(a[mi][3]),
                              "r"(b[ni][0]), "r"(b[ni][1]));
            }
            __syncthreads();
            if (it + NSTG < KIT) {
                int j = it + NSTG;
                int kA = (j < 8 ? j : j - 8) * BK;
                int kB = (j < 8 ? (j & 3) : j - 4) * BK;
#pragma unroll
                for (int i = 0; i < 4; i++) {
                    CP16(dA0 + st * A_ST_B + i * dstStep, aSrc + i * srcStep + kA);
                    CP16(dB0 + st * B_ST_B + i * dstStep, bSrc + i * srcStep + kB);
                }
            }
            CP_COMMIT();
            st = (st == NSTG - 1) ? 0 : st + 1;
        }

        // epilogue: D frag -> dest with bias (local cols 0..127)
        const int quad = lane >> 2, tq = lane & 3;
#pragma unroll
        for (int mi = 0; mi < 4; mi++) {
            int row = m0 + wm * 64 + mi * 16 + quad;
#pragma unroll
            for (int ni = 0; ni < 4; ni++) {
                int col = wn * 32 + ni * 8 + tq * 2;
                float2 bv = *(const float2*)(bias + col);
                float2 v0 = make_float2(d[mi][ni][0] + bv.x, d[mi][ni][1] + bv.y);
                float2 v1 = make_float2(d[mi][ni][2] + bv.x, d[mi][ni][3] + bv.y);
                *(float2*)&Cp[(size_t)row * cstride + col] = v0;
                *(float2*)&Cp[(size_t)(row + 8) * cstride + col] = v1;
            }
        }
    }
}

// ---------------------------------------------------------------------------
// Gather-mean over Hn rows: out[(b,n), 256:512] = mean_k Hn[b,idx[n,k],:]
// One block per n; 512 threads = 64 float4-lanes x 8 batches.
// launch_bounds(512,3) caps regs at 42 so blocks co-reside with GEMM CTAs.
// ---------------------------------------------------------------------------
__global__ __launch_bounds__(512, 3) void gather_out_kernel(
    const float* __restrict__ Hn, const int* __restrict__ idx,
    float* __restrict__ out)
{
    __shared__ int sidx[Kn];
    const int n = blockIdx.x, t = threadIdx.x;
    if (t < Kn) sidx[t] = idx[n * Kn + t] * 64;   // prescaled float4 row offset
    __syncthreads();

    const int f4 = t & 63;
    const int b  = t >> 6;             // 0..7
    const float4* hb = (const float4*)Hn + (size_t)b * Nn * 64 + f4;

    float4 a0 = {0,0,0,0}, a1 = {0,0,0,0};
#pragma unroll
    for (int k = 0; k < Kn; k += 2) {
        float4 v0 = hb[sidx[k + 0]];
        float4 v1 = hb[sidx[k + 1]];
        a0.x += v0.x; a0.y += v0.y; a0.z += v0.z; a0.w += v0.w;
        a1.x += v1.x; a1.y += v1.y; a1.z += v1.z; a1.w += v1.w;
    }
    const float s = 1.0f / Kn;
    float4 m = make_float4((a0.x + a1.x) * s, (a0.y + a1.y) * s,
                           (a0.z + a1.z) * s, (a0.w + a1.w) * s);
    ((float4*)(out + ((size_t)b * Nn + n) * Cch + 256))[f4] = m;
}

// ---------------------------------------------------------------------------
// Persistent fused epilogue (unchanged).
// ---------------------------------------------------------------------------
#define EPI_BLOCKS 128
#define EPI_ROWS   (Mrows / EPI_BLOCKS)   // 128 rows per block, 16 per warp

__global__ __launch_bounds__(256) void epilogue_kernel(
    const float* __restrict__ gamma, const float* __restrict__ beta,
    float* __restrict__ h)
{
    __shared__ float ssum[Cch], ssq[Cch];
    __shared__ float sinv[EPI_ROWS];
    __shared__ float sc[Cch], sh[Cch];
    __shared__ int slast;
    const int tid = threadIdx.x, lane = tid & 31, wid = tid >> 5;
    ssum[tid] = 0.f; ssq[tid] = 0.f;
    ssum[tid + 256] = 0.f; ssq[tid + 256] = 0.f;
    __syncthreads();

    float asum[4][4], asq[4][4];
#pragma unroll
    for (int q = 0; q < 4; q++)
#pragma unroll
        for (int j = 0; j < 4; j++) { asum[q][j] = 0.f; asq[q][j] = 0.f; }

    const int rbase = wid * 16;
    const int row0 = blockIdx.x * EPI_ROWS + rbase;
#pragma unroll 1
    for (int r = 0; r < 16; r++) {
        const float4* p = (const float4*)(h + (size_t)(row0 + r) * Cch);
        float4 v[4];
#pragma unroll
        for (int q = 0; q < 4; q++) v[q] = p[lane + 32 * q];
        float s = 0.f;
#pragma unroll
        for (int q = 0; q < 4; q++)
            s += v[q].x * v[q].x + v[q].y * v[q].y + v[q].z * v[q].z + v[q].w * v[q].w;
#pragma unroll
        for (int o = 16; o; o >>= 1) s += __shfl_xor_sync(0xffffffffu, s, o);
        float inv = 1.0f / fmaxf(sqrtf(s), 1e-12f);
        if (lane == 0) sinv[rbase + r] = inv;
#pragma unroll
        for (int q = 0; q < 4; q++) {
            float u[4] = {v[q].x, v[q].y, v[q].z, v[q].w};
#pragma unroll
            for (int j = 0; j < 4; j++) {
                float t = fmaxf(u[j] * inv, 0.0f);
                asum[q][j] += t;
                asq[q][j]  += t * t;
            }
        }
    }
#pragma unroll
    for (int q = 0; q < 4; q++)
#pragma unroll
        for (int j = 0; j < 4; j++) {
            int c = 4 * lane + 128 * q + j;
            atomicAdd(&ssum[c], asum[q][j]);
            atomicAdd(&ssq[c],  asq[q][j]);
        }
    __syncthreads();
    for (int c = tid; c < Cch; c += 256) {
        atomicAdd(&g_stats[c],       ssum[c]);
        atomicAdd(&g_stats[Cch + c], ssq[c]);
    }

    // ---- grid barrier ----
    __threadfence();
    __syncthreads();
    if (tid == 0) {
        atomicAdd(&g_bar0, 1);
        while (*(volatile int*)&g_bar0 < EPI_BLOCKS) { }
    }
    __syncthreads();
    __threadfence();

    // ---- finalize (every block; values into smem) ----
    const float invM = 1.0f / (float)Mrows;
    for (int c = tid; c < Cch; c += 256) {
        float mu  = g_stats[c] * invM;
        float var = g_stats[Cch + c] * invM - mu * mu;
        float s   = gamma[c] * rsqrtf(var + 1e-5f);
        sc[c] = s;
        sh[c] = beta[c] - mu * s;
    }
    __syncthreads();

    // ---- self-clean: last block to finish reading zeroes stats + counters ----
    if (tid == 0) slast = (atomicAdd(&g_done, 1) == EPI_BLOCKS - 1);
    __syncthreads();
    if (slast) {
        for (int c = tid; c < 2 * Cch; c += 256) g_stats[c] = 0.f;
        if (tid == 0) { g_bar0 = 0; g_done = 0; }
    }

    // ---- phase 2: apply on the same rows ----
#pragma unroll 1
    for (int r = 0; r < 16; r++) {
        const float inv = sinv[rbase + r];
        float4* p = (float4*)(h + (size_t)(row0 + r) * Cch);
#pragma unroll
        for (int q = 0; q < 4; q++) {
            float4 v = p[lane + 32 * q];
            int c = 4 * lane + 128 * q;
            v.x = fmaxf(v.x * inv, 0.f) * sc[c + 0] + sh[c + 0];
            v.y = fmaxf(v.y * inv, 0.f) * sc[c + 1] + sh[c + 1];
            v.z = fmaxf(v.z * inv, 0.f) * sc[c + 2] + sh[c + 2];
            v.w = fmaxf(v.w * inv, 0.f) * sc[c + 3] + sh[c + 3];
            p[lane + 32 * q] = v;
        }
    }
}

// ---------------------------------------------------------------------------
// Launch
// Inputs: x, idx_neib, Wx_w, Wx_b, Wn_w, Wn_b, gamma, beta
// ---------------------------------------------------------------------------
extern "C" void kernel_launch(void* const* d_in, const int* in_sizes, int n_in,
                              void* d_out, int out_size)
{
    const float* x     = (const float*)d_in[0];
    const int*   idx   = (const int*)  d_in[1];
    const float* Wx_w  = (const float*)d_in[2];
    const float* Wx_b  = (const float*)d_in[3];
    const float* Wn_w  = (const float*)d_in[4];
    const float* Wn_b  = (const float*)d_in[5];
    const float* gamma = (const float*)d_in[6];
    const float* beta  = (const float*)d_in[7];
    float* out = (float*)d_out;

    static cudaStream_t s2 = nullptr;
    static cudaEvent_t ev_n = nullptr, ev_join = nullptr;
    static int stream_ok = -1;
    if (stream_ok < 0) {
        bool ok = cudaFuncSetAttribute(gemm_mma_kernel,
                     cudaFuncAttributeMaxDynamicSharedMemorySize, GEMM_SMEM) == cudaSuccess;
        ok = ok && cudaStreamCreateWithFlags(&s2, cudaStreamNonBlocking) == cudaSuccess;
        ok = ok && cudaEventCreateWithFlags(&ev_n, cudaEventDisableTiming) == cudaSuccess;
        ok = ok && cudaEventCreateWithFlags(&ev_join, cudaEventDisableTiming) == cudaSuccess;
        stream_ok = ok ? 1 : 0;
    }

    __nv_bfloat16* Wimg;  cudaGetSymbolAddress((void**)&Wimg, g_Wbf);   // [512, Kimg]
    __nv_bfloat16* Aself; cudaGetSymbolAddress((void**)&Aself, g_Aself);
    float* Hn; cudaGetSymbolAddress((void**)&Hn, g_Hn);

    // operand prep
    convW_kernel<<<64, 256>>>(Wx_w, Wn_w);
    convA_kernel<<<2048, 256>>>(x);

    // neighbor half first: Hn = x * Wn^T + bn   (grid (128,2), one tile each)
    gemm_mma_kernel<<<dim3(128, 2), 256, GEMM_SMEM>>>(
        Aself, Wimg, Wx_b, Wn_b, out, Hn, 2, 1);

    if (stream_ok) {
        // co-run: persistent self-GEMM (128 CTAs, 1/SM) + gather backfill
        cudaEventRecord(ev_n, 0);
        gemm_mma_kernel<<<dim3(128, 1), 256, GEMM_SMEM>>>(
            Aself, Wimg, Wx_b, Wn_b, out, Hn, 0, 2);
        cudaStreamWaitEvent(s2, ev_n, 0);
        gather_out_kernel<<<Nn, 512, 0, s2>>>(Hn, idx, out);
        cudaEventRecord(ev_join, s2);
        cudaStreamWaitEvent(0, ev_join, 0);
    } else {
        gather_out_kernel<<<Nn, 512>>>(Hn, idx, out);
        gemm_mma_kernel<<<dim3(128, 1), 256, GEMM_SMEM>>>(
            Aself, Wimg, Wx_b, Wn_b, out, Hn, 0, 2);
    }

    epilogue_kernel<<<EPI_BLOCKS, 256>>>(gamma, beta, out);
}